// round 1
// baseline (speedup 1.0000x reference)
#include <cuda_runtime.h>

#define THREADS 256

namespace {
constexpr int B_   = 2;
constexpr int H_   = 16;
constexpr int N_   = 4096;
constexpr int D_   = 128;
constexpr int CHK  = 128;
constexpr int NBLK = N_ / CHK;        // 32 chunks
constexpr int BHc  = B_ * H_;         // 32
constexpr int NCTA = BHc * NBLK;      // 1024
}

// Scratch for per-chunk state contributions / prefix states (64 MB).
__device__ float g_states[(size_t)NCTA * D_ * D_];

// ---------------------------------------------------------------------------
// Kernel 1: KdV_c[d][e] = sum_s k[s,d] * exp(-sl*(CHK-s)) * v[s,e]
// one CTA per (b,h,chunk); square 128x128x128 GEMM, no transposes needed.
// ---------------------------------------------------------------------------
__global__ void __launch_bounds__(THREADS, 1)
kdv_kernel(const float* __restrict__ k_g, const float* __restrict__ v_g,
           const float* __restrict__ s_g)
{
    extern __shared__ float sm[];
    float* ks = sm;               // [128][128], k scaled by kdec[s]
    float* vs = sm + CHK * D_;    // [128][128]

    const int tid = threadIdx.x;
    const int bhc = blockIdx.x;
    const int c   = bhc & (NBLK - 1);
    const int bh  = bhc >> 5;
    const int h   = bh & (H_ - 1);
    const float sl = s_g[h];

    const size_t cbase = ((size_t)bh * N_ + (size_t)c * CHK) * D_;
    const float4* k4 = reinterpret_cast<const float4*>(k_g + cbase);
    const float4* v4 = reinterpret_cast<const float4*>(v_g + cbase);

    #pragma unroll 4
    for (int i = tid; i < CHK * D_ / 4; i += THREADS) {
        int r = i >> 5;                               // s row (32 float4/row)
        float kd = expf(-sl * (float)(CHK - r));
        float4 a = k4[i];
        a.x *= kd; a.y *= kd; a.z *= kd; a.w *= kd;
        reinterpret_cast<float4*>(ks)[i] = a;
        reinterpret_cast<float4*>(vs)[i] = v4[i];
    }
    __syncthreads();

    const int tx = tid & 15, ty = tid >> 4;
    const int d0 = ty * 8, e0 = tx * 8;
    float acc[8][8];
    #pragma unroll
    for (int i = 0; i < 8; i++)
        #pragma unroll
        for (int j = 0; j < 8; j++) acc[i][j] = 0.f;

    #pragma unroll 4
    for (int s = 0; s < CHK; s++) {
        float a[8], b[8];
        *reinterpret_cast<float4*>(&a[0]) = *reinterpret_cast<const float4*>(&ks[s * D_ + d0]);
        *reinterpret_cast<float4*>(&a[4]) = *reinterpret_cast<const float4*>(&ks[s * D_ + d0 + 4]);
        *reinterpret_cast<float4*>(&b[0]) = *reinterpret_cast<const float4*>(&vs[s * D_ + e0]);
        *reinterpret_cast<float4*>(&b[4]) = *reinterpret_cast<const float4*>(&vs[s * D_ + e0 + 4]);
        #pragma unroll
        for (int i = 0; i < 8; i++)
            #pragma unroll
            for (int j = 0; j < 8; j++) acc[i][j] += a[i] * b[j];
    }

    float* outp = g_states + (size_t)bhc * D_ * D_;
    #pragma unroll
    for (int i = 0; i < 8; i++) {
        #pragma unroll
        for (int j = 0; j < 8; j += 4) {
            float4 w = make_float4(acc[i][j], acc[i][j+1], acc[i][j+2], acc[i][j+3]);
            *reinterpret_cast<float4*>(&outp[(d0 + i) * D_ + e0 + j]) = w;
        }
    }
}

// ---------------------------------------------------------------------------
// Kernel 2: in-place exclusive decay scan over chunks:
//   run = 0; for c: tmp = buf[c]; buf[c] = run; run = bd*run + tmp
// grid = BHc * 8 (each CTA owns a 16-column slice of the 128x128 state)
// ---------------------------------------------------------------------------
__global__ void __launch_bounds__(THREADS, 1)
scan_kernel(const float* __restrict__ s_g)
{
    const int bh  = blockIdx.x >> 3;
    const int sli = blockIdx.x & 7;
    const int h   = bh & (H_ - 1);
    const float bd = expf(-s_g[h] * (float)CHK);
    const int tid = threadIdx.x;

    // 512 float4 units per slice; thread owns u = tid and u = tid+256
    int u0 = tid,        d0 = u0 >> 2, q0 = u0 & 3;
    int u1 = tid + 256,  d1 = u1 >> 2, q1 = u1 & 3;
    const int off0 = d0 * (D_ / 4) + sli * 4 + q0;
    const int off1 = d1 * (D_ / 4) + sli * 4 + q1;

    float4* base = reinterpret_cast<float4*>(g_states) + (size_t)bh * NBLK * (D_ * D_ / 4);
    float4 r0 = make_float4(0.f, 0.f, 0.f, 0.f);
    float4 r1 = r0;
    for (int cc = 0; cc < NBLK; cc++) {
        float4* p = base + (size_t)cc * (D_ * D_ / 4);
        float4 t0 = p[off0], t1 = p[off1];
        p[off0] = r0;  p[off1] = r1;
        r0.x = bd * r0.x + t0.x;  r0.y = bd * r0.y + t0.y;
        r0.z = bd * r0.z + t0.z;  r0.w = bd * r0.w + t0.w;
        r1.x = bd * r1.x + t1.x;  r1.y = bd * r1.y + t1.y;
        r1.z = bd * r1.z + t1.z;  r1.w = bd * r1.w + t1.w;
    }
}

// ---------------------------------------------------------------------------
// Kernel 3: per (b,h,chunk):
//   scores[t][s] = mask(t>=s) * dtab[t-s] * sum_d q[t,d] k[s,d]
//   o[t][e] = sum_s scores[t][s] v[s][e] + dtab[t] * sum_d q[t,d] S_in[d][e]
// smem: qT (pad129), kT (pad129, reused as scores^T), vS (S then v), dtab
// ---------------------------------------------------------------------------
__global__ void __launch_bounds__(THREADS, 1)
out_kernel(const float* __restrict__ q_g, const float* __restrict__ k_g,
           const float* __restrict__ v_g, const float* __restrict__ s_g,
           float* __restrict__ o_g)
{
    extern __shared__ float sm[];
    float* qT   = sm;                                   // [128][129]
    float* kT   = sm + 128 * 129;                       // [128][129] -> scT [128][128]
    float* vS   = sm + 2 * 128 * 129;                   // [128][128] (S then v)
    float* dtab = sm + 2 * 128 * 129 + 128 * 128;       // [128]

    const int tid = threadIdx.x;
    const int bhc = blockIdx.x;
    const int c   = bhc & (NBLK - 1);
    const int bh  = bhc >> 5;
    const int h   = bh & (H_ - 1);
    const float sl = s_g[h];
    const size_t cbase = ((size_t)bh * N_ + (size_t)c * CHK) * D_;

    if (tid < 128) dtab[tid] = expf(-sl * (float)tid);

    // load + transpose q,k (conflict-free writes via pad 129), load S raw
    {
        const float* qc = q_g + cbase;
        const float* kc = k_g + cbase;
        #pragma unroll 4
        for (int i = tid; i < CHK * D_; i += THREADS) {
            int t = i >> 7, d = i & 127;
            qT[d * 129 + t] = qc[i];
            kT[d * 129 + t] = kc[i];
        }
        const float4* S4 = reinterpret_cast<const float4*>(g_states + (size_t)bhc * D_ * D_);
        #pragma unroll 4
        for (int i = tid; i < CHK * D_ / 4; i += THREADS)
            reinterpret_cast<float4*>(vS)[i] = S4[i];
    }
    __syncthreads();

    const int tx = tid & 15, ty = tid >> 4;
    const int t0 = ty * 8;

    // ---- GEMM A: scores^T (t rows contiguous per thread, s interleaved by tx)
    float acc[8][8];
    #pragma unroll
    for (int i = 0; i < 8; i++)
        #pragma unroll
        for (int j = 0; j < 8; j++) acc[i][j] = 0.f;

    #pragma unroll 2
    for (int d = 0; d < D_; d++) {
        float a[8], b[8];
        #pragma unroll
        for (int i = 0; i < 8; i++) a[i] = qT[d * 129 + t0 + i];
        #pragma unroll
        for (int j = 0; j < 8; j++) b[j] = kT[d * 129 + tx + 16 * j];
        #pragma unroll
        for (int i = 0; i < 8; i++)
            #pragma unroll
            for (int j = 0; j < 8; j++) acc[i][j] += a[i] * b[j];
    }
    __syncthreads();           // all reads of kT complete before overwrite

    // mask + decay, write scores^T into kT buffer as scT[s*128 + t]
    float* scT = kT;
    #pragma unroll
    for (int j = 0; j < 8; j++) {
        int s = tx + 16 * j;
        float w[8];
        #pragma unroll
        for (int i = 0; i < 8; i++) {
            int df = t0 + i - s;
            w[i] = (df >= 0) ? acc[i][j] * dtab[df] : 0.f;
        }
        *reinterpret_cast<float4*>(&scT[s * D_ + t0])     = make_float4(w[0], w[1], w[2], w[3]);
        *reinterpret_cast<float4*>(&scT[s * D_ + t0 + 4]) = make_float4(w[4], w[5], w[6], w[7]);
    }
    __syncthreads();

    // ---- GEMM B (inter): o = (q @ S_in), then scale rows by dtab[t]
    const int e0 = tx * 8;
    float o[8][8];
    #pragma unroll
    for (int i = 0; i < 8; i++)
        #pragma unroll
        for (int j = 0; j < 8; j++) o[i][j] = 0.f;

    #pragma unroll 2
    for (int d = 0; d < D_; d++) {
        float a[8], b[8];
        #pragma unroll
        for (int i = 0; i < 8; i++) a[i] = qT[d * 129 + t0 + i];
        *reinterpret_cast<float4*>(&b[0]) = *reinterpret_cast<const float4*>(&vS[d * D_ + e0]);
        *reinterpret_cast<float4*>(&b[4]) = *reinterpret_cast<const float4*>(&vS[d * D_ + e0 + 4]);
        #pragma unroll
        for (int i = 0; i < 8; i++)
            #pragma unroll
            for (int j = 0; j < 8; j++) o[i][j] += a[i] * b[j];
    }
    #pragma unroll
    for (int i = 0; i < 8; i++) {
        float f = dtab[t0 + i];
        #pragma unroll
        for (int j = 0; j < 8; j++) o[i][j] *= f;
    }
    __syncthreads();           // all reads of S complete before overwrite

    // overwrite vS with v chunk
    {
        const float4* v4 = reinterpret_cast<const float4*>(v_g + cbase);
        #pragma unroll 4
        for (int i = tid; i < CHK * D_ / 4; i += THREADS)
            reinterpret_cast<float4*>(vS)[i] = v4[i];
    }
    __syncthreads();

    // ---- GEMM C (intra): o += scores @ v
    #pragma unroll 2
    for (int s = 0; s < CHK; s++) {
        float a[8], b[8];
        *reinterpret_cast<float4*>(&a[0]) = *reinterpret_cast<const float4*>(&scT[s * D_ + t0]);
        *reinterpret_cast<float4*>(&a[4]) = *reinterpret_cast<const float4*>(&scT[s * D_ + t0 + 4]);
        *reinterpret_cast<float4*>(&b[0]) = *reinterpret_cast<const float4*>(&vS[s * D_ + e0]);
        *reinterpret_cast<float4*>(&b[4]) = *reinterpret_cast<const float4*>(&vS[s * D_ + e0 + 4]);
        #pragma unroll
        for (int i = 0; i < 8; i++)
            #pragma unroll
            for (int j = 0; j < 8; j++) o[i][j] += a[i] * b[j];
    }

    float* oc = o_g + cbase;
    #pragma unroll
    for (int i = 0; i < 8; i++) {
        #pragma unroll
        for (int j = 0; j < 8; j += 4) {
            float4 w = make_float4(o[i][j], o[i][j+1], o[i][j+2], o[i][j+3]);
            *reinterpret_cast<float4*>(&oc[(t0 + i) * D_ + e0 + j]) = w;
        }
    }
}

// ---------------------------------------------------------------------------
extern "C" void kernel_launch(void* const* d_in, const int* in_sizes, int n_in,
                              void* d_out, int out_size)
{
    const float* q = (const float*)d_in[0];
    const float* k = (const float*)d_in[1];
    const float* v = (const float*)d_in[2];
    const float* s = (const float*)d_in[3];
    float* o = (float*)d_out;

    const int smem_kdv = CHK * D_ * 2 * (int)sizeof(float);                       // 131072
    const int smem_out = (2 * 128 * 129 + 128 * 128 + 128) * (int)sizeof(float);  // 198144

    cudaFuncSetAttribute(kdv_kernel, cudaFuncAttributeMaxDynamicSharedMemorySize, smem_kdv);
    cudaFuncSetAttribute(out_kernel, cudaFuncAttributeMaxDynamicSharedMemorySize, smem_out);

    kdv_kernel<<<NCTA, THREADS, smem_kdv>>>(k, v, s);
    scan_kernel<<<BHc * 8, THREADS>>>(s);
    out_kernel<<<NCTA, THREADS, smem_out>>>(q, k, v, s, o);
}

// round 4
// speedup vs baseline: 1.8491x; 1.8491x over previous
#include <cuda_runtime.h>
#include <cstdint>

#define THREADS 256

namespace {
constexpr int H_   = 16;
constexpr int N_   = 4096;
constexpr int D_   = 128;
constexpr int CHK  = 128;
constexpr int NBLK = 32;
constexpr int BHc  = 32;
constexpr int NCTA = 1024;

constexpr int ST   = 132;            // smem row stride in floats (4 mod 32)
constexpr int BUFN = ST * 128;       // floats per 128-row tile buffer = 16896

// smem float-index offsets
constexpr int F_TAB = 0;             // 128 floats
constexpr int F_A   = 128;           // tile buffer A
constexpr int F_B   = F_A + BUFN;    // tile buffer B (k -> S -> v in out kernel)
constexpr int F_SC  = F_B + BUFN;    // scores tile (out kernel only)

constexpr int SMEM_KDV = (F_SC) * 4;            // 136192 B
constexpr int SMEM_OUT = (F_SC + BUFN) * 4;     // 203776 B
}

__device__ float g_states[(size_t)NCTA * D_ * D_];

// ---------------------------------------------------------------------------
__device__ __forceinline__ uint32_t f2tf(float x) {
    uint32_t u;
    asm("cvt.rna.tf32.f32 %0, %1;" : "=r"(u) : "f"(x));
    return u;
}

// D += A*B ; m16n8k8 tf32
__device__ __forceinline__ void mma8(float* d, const uint32_t* a, const uint32_t* b) {
    asm volatile(
        "mma.sync.aligned.m16n8k8.row.col.f32.tf32.tf32.f32 "
        "{%0,%1,%2,%3}, {%4,%5,%6,%7}, {%8,%9}, {%0,%1,%2,%3};"
        : "+f"(d[0]), "+f"(d[1]), "+f"(d[2]), "+f"(d[3])
        : "r"(a[0]), "r"(a[1]), "r"(a[2]), "r"(a[3]), "r"(b[0]), "r"(b[1]));
}

// Fragment loaders. g = lane>>2, c = lane&3.
// K-major tile T[row][k] (stride ST):
__device__ __forceinline__ void fragA_K(const float* T, int m0, int k0, int g, int c, uint32_t* a) {
    const float* p = T + (m0 + g) * ST + k0 + c;
    a[0] = __float_as_uint(p[0]);
    a[2] = __float_as_uint(p[4]);
    p += 8 * ST;
    a[1] = __float_as_uint(p[0]);
    a[3] = __float_as_uint(p[4]);
}
__device__ __forceinline__ void fragB_K(const float* T, int n0, int k0, int g, int c, uint32_t* b) {
    const float* p = T + (n0 + g) * ST + k0 + c;
    b[0] = __float_as_uint(p[0]);
    b[1] = __float_as_uint(p[4]);
}
// Transposed storage T[k][m] (natural [s][e] layouts):
__device__ __forceinline__ void fragA_T(const float* T, int m0, int k0, int g, int c, uint32_t* a) {
    const float* p = T + (k0 + c) * ST + m0 + g;
    a[0] = __float_as_uint(p[0]);
    a[1] = __float_as_uint(p[8]);
    p += 4 * ST;
    a[2] = __float_as_uint(p[0]);
    a[3] = __float_as_uint(p[8]);
}
__device__ __forceinline__ void fragB_T(const float* T, int n0, int k0, int g, int c, uint32_t* b) {
    const float* p = T + (k0 + c) * ST + n0 + g;
    b[0] = __float_as_uint(p[0]);
    b[1] = __float_as_uint(p[4 * ST]);
}

// gmem fp32 [r][c] (128x128, row stride 128) -> smem tf32 [r][c] stride ST.
// optional per-row scale (smem table) applied before cvt.
__device__ __forceinline__ void load_nat(const float* __restrict__ src, float* dst,
                                         const float* rowscale) {
    #pragma unroll 4
    for (int i = threadIdx.x; i < 128 * 32; i += THREADS) {
        int r = i >> 5, c4 = (i & 31) << 2;
        float4 f = *reinterpret_cast<const float4*>(src + r * 128 + c4);
        float s = rowscale ? rowscale[r] : 1.0f;
        float4 w;
        w.x = __uint_as_float(f2tf(f.x * s));
        w.y = __uint_as_float(f2tf(f.y * s));
        w.z = __uint_as_float(f2tf(f.z * s));
        w.w = __uint_as_float(f2tf(f.w * s));
        *reinterpret_cast<float4*>(dst + r * ST + c4) = w;
    }
}

// 128x128x128 GEMM: acc[mt][nt][4] += A*B. AT/BT select transposed-storage frags.
template <bool AT, bool BT>
__device__ __forceinline__ void gemm128(const float* A, const float* B,
                                        float acc[2][8][4], int m0w, int n0w,
                                        int g, int c) {
    #pragma unroll 4
    for (int ks = 0; ks < 16; ks++) {
        const int k0 = ks * 8;
        uint32_t af[2][4];
        #pragma unroll
        for (int mt = 0; mt < 2; mt++) {
            if (AT) fragA_T(A, m0w + mt * 16, k0, g, c, af[mt]);
            else    fragA_K(A, m0w + mt * 16, k0, g, c, af[mt]);
        }
        #pragma unroll
        for (int nt = 0; nt < 8; nt++) {
            uint32_t bf[2];
            if (BT) fragB_T(B, n0w + nt * 8, k0, g, c, bf);
            else    fragB_K(B, n0w + nt * 8, k0, g, c, bf);
            mma8(acc[0][nt], af[0], bf);
            mma8(acc[1][nt], af[1], bf);
        }
    }
}

// ---------------------------------------------------------------------------
// Kernel 1: g_states[bhc][e][d] = sum_s v[s][e] * k[s][d] * exp(-sl*(CHK-s))
// ---------------------------------------------------------------------------
__global__ void __launch_bounds__(THREADS, 1)
kdv_kernel(const float* __restrict__ k_g, const float* __restrict__ v_g,
           const float* __restrict__ s_g)
{
    extern __shared__ float sm[];
    float* tab  = sm + F_TAB;
    float* bufV = sm + F_A;     // v natural [s][e]
    float* bufK = sm + F_B;     // k natural [s][d], scaled by kdec[s]

    const int tid = threadIdx.x;
    const int bhc = blockIdx.x;
    const int bh = bhc >> 5, h = bh & (H_ - 1);
    const float sl = s_g[h];
    const size_t cbase = ((size_t)bh * N_ + (size_t)(bhc & 31) * CHK) * D_;

    if (tid < 128) tab[tid] = expf(-sl * (float)(CHK - tid));
    __syncthreads();

    load_nat(v_g + cbase, bufV, nullptr);
    load_nat(k_g + cbase, bufK, tab);
    __syncthreads();

    const int lane = tid & 31, wid = tid >> 5;
    const int g = lane >> 2, c = lane & 3;
    const int m0w = (wid & 3) * 32, n0w = (wid >> 2) * 64;

    float acc[2][8][4];
    #pragma unroll
    for (int mt = 0; mt < 2; mt++)
        #pragma unroll
        for (int nt = 0; nt < 8; nt++)
            #pragma unroll
            for (int r = 0; r < 4; r++) acc[mt][nt][r] = 0.f;

    gemm128<true, true>(bufV, bufK, acc, m0w, n0w, g, c);   // A=v [s][e], B=k [s][d]

    float* outp = g_states + (size_t)bhc * D_ * D_;
    #pragma unroll
    for (int mt = 0; mt < 2; mt++) {
        int r0 = m0w + mt * 16 + g;
        #pragma unroll
        for (int nt = 0; nt < 8; nt++) {
            int col = n0w + nt * 8 + 2 * c;
            *reinterpret_cast<float2*>(outp + r0 * 128 + col) =
                make_float2(acc[mt][nt][0], acc[mt][nt][1]);
            *reinterpret_cast<float2*>(outp + (r0 + 8) * 128 + col) =
                make_float2(acc[mt][nt][2], acc[mt][nt][3]);
        }
    }
}

// ---------------------------------------------------------------------------
// Kernel 2: exclusive decay scan over chunks (elementwise on [e][d] states)
// ---------------------------------------------------------------------------
__global__ void __launch_bounds__(THREADS, 1)
scan_kernel(const float* __restrict__ s_g)
{
    const int bh  = blockIdx.x >> 3;
    const int sli = blockIdx.x & 7;
    const int h   = bh & (H_ - 1);
    const float bd = expf(-s_g[h] * (float)CHK);
    const int tid = threadIdx.x;

    int u0 = tid,       d0 = u0 >> 2, q0 = u0 & 3;
    int u1 = tid + 256, d1 = u1 >> 2, q1 = u1 & 3;
    const int off0 = d0 * 32 + sli * 4 + q0;
    const int off1 = d1 * 32 + sli * 4 + q1;

    float4* base = reinterpret_cast<float4*>(g_states) + (size_t)bh * NBLK * (D_ * D_ / 4);
    float4 r0 = make_float4(0.f, 0.f, 0.f, 0.f), r1 = r0;
    for (int cc = 0; cc < NBLK; cc++) {
        float4* p = base + (size_t)cc * (D_ * D_ / 4);
        float4 t0 = p[off0], t1 = p[off1];
        p[off0] = r0;  p[off1] = r1;
        r0.x = bd * r0.x + t0.x;  r0.y = bd * r0.y + t0.y;
        r0.z = bd * r0.z + t0.z;  r0.w = bd * r0.w + t0.w;
        r1.x = bd * r1.x + t1.x;  r1.y = bd * r1.y + t1.y;
        r1.z = bd * r1.z + t1.z;  r1.w = bd * r1.w + t1.w;
    }
}

// ---------------------------------------------------------------------------
// Kernel 3: per (b,h,chunk):
//   GEMM1: sc[t][s] = mask(t>=s) * exp(-sl(t-s)) * (q . k)
//   GEMM2: o  = exp(-sl t) * (q @ S)        (S stored [e][d] -> B K-major)
//   GEMM3: o += sc @ v                      (v natural [s][e] -> B transposed)
// ---------------------------------------------------------------------------
__global__ void __launch_bounds__(THREADS, 1)
out_kernel(const float* __restrict__ q_g, const float* __restrict__ k_g,
           const float* __restrict__ v_g, const float* __restrict__ s_g,
           float* __restrict__ o_g)
{
    extern __shared__ float sm[];
    float* tab  = sm + F_TAB;
    float* bufQ = sm + F_A;     // q [t][d]
    float* bufB = sm + F_B;     // k -> S -> v
    float* bufS = sm + F_SC;    // scores [t][s]

    const int tid = threadIdx.x;
    const int bhc = blockIdx.x;
    const int bh = bhc >> 5, h = bh & (H_ - 1);
    const float sl = s_g[h];
    const size_t cbase = ((size_t)bh * N_ + (size_t)(bhc & 31) * CHK) * D_;

    if (tid < 128) tab[tid] = expf(-sl * (float)tid);

    load_nat(q_g + cbase, bufQ, nullptr);
    load_nat(k_g + cbase, bufB, nullptr);
    __syncthreads();

    const int lane = tid & 31, wid = tid >> 5;
    const int g = lane >> 2, c = lane & 3;
    const int m0w = (wid & 3) * 32, n0w = (wid >> 2) * 64;

    float acc[2][8][4];
    #pragma unroll
    for (int mt = 0; mt < 2; mt++)
        #pragma unroll
        for (int nt = 0; nt < 8; nt++)
            #pragma unroll
            for (int r = 0; r < 4; r++) acc[mt][nt][r] = 0.f;

    // GEMM1: scores = q . k^T  (both K-major natural)
    gemm128<false, false>(bufQ, bufB, acc, m0w, n0w, g, c);

    // transform -> sc smem (mask + decay + tf32), zero acc
    #pragma unroll
    for (int mt = 0; mt < 2; mt++) {
        int t0 = m0w + mt * 16 + g, t1 = t0 + 8;
        #pragma unroll
        for (int nt = 0; nt < 8; nt++) {
            int s0 = n0w + nt * 8 + 2 * c;
            float w00 = (t0 >= s0)     ? acc[mt][nt][0] * tab[t0 - s0]     : 0.f;
            float w01 = (t0 >= s0 + 1) ? acc[mt][nt][1] * tab[t0 - s0 - 1] : 0.f;
            float w10 = (t1 >= s0)     ? acc[mt][nt][2] * tab[t1 - s0]     : 0.f;
            float w11 = (t1 >= s0 + 1) ? acc[mt][nt][3] * tab[t1 - s0 - 1] : 0.f;
            bufS[t0 * ST + s0]     = __uint_as_float(f2tf(w00));
            bufS[t0 * ST + s0 + 1] = __uint_as_float(f2tf(w01));
            bufS[t1 * ST + s0]     = __uint_as_float(f2tf(w10));
            bufS[t1 * ST + s0 + 1] = __uint_as_float(f2tf(w11));
            acc[mt][nt][0] = acc[mt][nt][1] = acc[mt][nt][2] = acc[mt][nt][3] = 0.f;
        }
    }
    __syncthreads();                               // k reads + sc writes done

    // S -> bufB
    load_nat(g_states + (size_t)bhc * D_ * D_, bufB, nullptr);
    __syncthreads();

    // GEMM2: inter = q @ S   (S[e][d] is K-major for n=e, k=d)
    gemm128<false, false>(bufQ, bufB, acc, m0w, n0w, g, c);

    // scale inter rows by exp(-sl*t)
    #pragma unroll
    for (int mt = 0; mt < 2; mt++) {
        float f0 = tab[m0w + mt * 16 + g];
        float f1 = tab[m0w + mt * 16 + g + 8];
        #pragma unroll
        for (int nt = 0; nt < 8; nt++) {
            acc[mt][nt][0] *= f0;  acc[mt][nt][1] *= f0;
            acc[mt][nt][2] *= f1;  acc[mt][nt][3] *= f1;
        }
    }
    __syncthreads();                               // S reads done

    // v -> bufB
    load_nat(v_g + cbase, bufB, nullptr);
    __syncthreads();

    // GEMM3: o += sc @ v   (sc K-major [t][s]; v natural [s][e] -> transposed B)
    gemm128<false, true>(bufS, bufB, acc, m0w, n0w, g, c);

    float* oc = o_g + cbase;
    #pragma unroll
    for (int mt = 0; mt < 2; mt++) {
        int r0 = m0w + mt * 16 + g;
        #pragma unroll
        for (int nt = 0; nt < 8; nt++) {
            int col = n0w + nt * 8 + 2 * c;
            *reinterpret_cast<float2*>(oc + r0 * 128 + col) =
                make_float2(acc[mt][nt][0], acc[mt][nt][1]);
            *reinterpret_cast<float2*>(oc + (r0 + 8) * 128 + col) =
                make_float2(acc[mt][nt][2], acc[mt][nt][3]);
        }
    }
}

// ---------------------------------------------------------------------------
extern "C" void kernel_launch(void* const* d_in, const int* in_sizes, int n_in,
                              void* d_out, int out_size)
{
    const float* q = (const float*)d_in[0];
    const float* k = (const float*)d_in[1];
    const float* v = (const float*)d_in[2];
    const float* s = (const float*)d_in[3];
    float* o = (float*)d_out;

    cudaFuncSetAttribute(kdv_kernel, cudaFuncAttributeMaxDynamicSharedMemorySize, SMEM_KDV);
    cudaFuncSetAttribute(out_kernel, cudaFuncAttributeMaxDynamicSharedMemorySize, SMEM_OUT);

    kdv_kernel<<<NCTA, THREADS, SMEM_KDV>>>(k, v, s);
    scan_kernel<<<BHc * 8, THREADS>>>(s);
    out_kernel<<<NCTA, THREADS, SMEM_OUT>>>(q, k, v, s, o);
}